// round 15
// baseline (speedup 1.0000x reference)
#include <cuda_runtime.h>
#include <math.h>
#include <float.h>

#define BB 8
#define NN 4096
#define SS 1024
#define KK 32
#define PP (BB*SS*KK)
#define BS (BB*SS)

__device__ float d_newxyz[BS*3];
__device__ int   d_fpsidx[BS];
__device__ int   d_knn[PP];
__device__ float d_geo[(size_t)PP*7];
__device__ float d_augy[(size_t)PP*32];
__device__ float d_ptsT[(size_t)BB*NN*64];
__device__ float d_fx1[(size_t)BS*96];
__device__ float d_y1[(size_t)PP*64];
__device__ float d_fy1[(size_t)BS*64];
__device__ float d_y2[(size_t)PP*128];
__device__ float d_fy2[(size_t)BS*128];
__device__ float d_cf[(size_t)BS*128];
__device__ float d_y3[(size_t)PP*128];
__device__ float d_part[4096*128];
__device__ float d_bnp_aug[64];
__device__ float d_bnp1[128];
__device__ float d_bnp1f[128];
__device__ float d_bnp2[256];
__device__ float d_bnp2f[256];
__device__ float d_bnp3[256];

// ---- transpose points (B,64,N) -> (B,N,64) ----
__global__ void k_ptsT(const float* __restrict__ pts) {
    __shared__ float t[32][33];
    int b = blockIdx.z, c0 = blockIdx.y*32, n0 = blockIdx.x*32;
    int tx = threadIdx.x, ty = threadIdx.y;
    #pragma unroll
    for (int i = 0; i < 32; i += 8)
        t[ty+i][tx] = pts[(size_t)b*64*NN + (size_t)(c0+ty+i)*NN + n0 + tx];
    __syncthreads();
    #pragma unroll
    for (int i = 0; i < 32; i += 8)
        d_ptsT[((size_t)b*NN + n0+ty+i)*64 + c0+tx] = t[tx][ty+i];
}

__device__ __forceinline__ unsigned redux_max_u32(unsigned v) {
    unsigned r;
    asm volatile("redux.sync.max.u32 %0, %1, 0xffffffff;" : "=r"(r) : "r"(v));
    return r;
}
__device__ __forceinline__ unsigned redux_min_u32(unsigned v) {
    unsigned r;
    asm volatile("redux.sync.min.u32 %0, %1, 0xffffffff;" : "=r"(r) : "r"(v));
    return r;
}

__device__ __forceinline__ unsigned long long pk2(float lo, float hi) {
    unsigned long long r;
    asm("mov.b64 %0, {%1, %2};" : "=l"(r) : "f"(lo), "f"(hi));
    return r;
}
__device__ __forceinline__ void upk2(unsigned long long v, float& lo, float& hi) {
    asm("mov.b64 {%0, %1}, %2;" : "=f"(lo), "=f"(hi) : "l"(v));
}
#define ADD2(o,a,b) asm("add.rn.f32x2 %0, %1, %2;" : "=l"(o) : "l"(a), "l"(b))
#define MUL2(o,a,b) asm("mul.rn.f32x2 %0, %1, %2;" : "=l"(o) : "l"(a), "l"(b))

// ---- FPS: 512 threads x 8 pts, packed f32x2 math, tree argmax ----
__global__ void __launch_bounds__(512) k_fps(const float* __restrict__ xyz,
                                             float* __restrict__ out) {
    int b = blockIdx.x, tid = threadIdx.x;
    int w = tid >> 5, lane = tid & 31;
    const float* xb = xyz + (size_t)b*3*NN;
    unsigned long long pxp[4], pyp[4], pzp[4];
    float dist[8];
    #pragma unroll
    for (int j = 0; j < 4; j++) {
        int n0 = (2*j)*512 + tid, n1 = (2*j+1)*512 + tid;
        pxp[j] = pk2(xb[n0],      xb[n1]);
        pyp[j] = pk2(xb[NN+n0],   xb[NN+n1]);
        pzp[j] = pk2(xb[2*NN+n0], xb[2*NN+n1]);
        dist[2*j] = 1e10f; dist[2*j+1] = 1e10f;
    }
    __shared__ unsigned long long red[2][16];
    int far = 0;
    for (int it = 0; it < SS; it++) {
        float cx = xb[far], cy = xb[NN+far], cz = xb[2*NN+far];
        if (tid == 0) {
            d_fpsidx[b*SS+it] = far;
            d_newxyz[((size_t)b*SS+it)*3+0] = cx;
            d_newxyz[((size_t)b*SS+it)*3+1] = cy;
            d_newxyz[((size_t)b*SS+it)*3+2] = cz;
            out[b*3072 + it]        = cx;
            out[b*3072 + 1024 + it] = cy;
            out[b*3072 + 2048 + it] = cz;
        }
        unsigned long long ncx = pk2(-cx, -cx);
        unsigned long long ncy = pk2(-cy, -cy);
        unsigned long long ncz = pk2(-cz, -cz);
        #pragma unroll
        for (int j = 0; j < 4; j++) {
            unsigned long long dx, dy, dz, mx, my, mz, s;
            ADD2(dx, pxp[j], ncx);
            ADD2(dy, pyp[j], ncy);
            ADD2(dz, pzp[j], ncz);
            MUL2(mx, dx, dx);
            MUL2(my, dy, dy);
            MUL2(mz, dz, dz);
            ADD2(s, mx, my);
            ADD2(s, s, mz);
            float d0, d1; upk2(s, d0, d1);
            dist[2*j]   = fminf(dist[2*j],   d0);
            dist[2*j+1] = fminf(dist[2*j+1], d1);
        }
        // log-depth fmax tree + ascending-slot index recovery (smallest n on tie)
        float a0 = fmaxf(dist[0], dist[1]);
        float a1 = fmaxf(dist[2], dist[3]);
        float a2 = fmaxf(dist[4], dist[5]);
        float a3 = fmaxf(dist[6], dist[7]);
        float b0 = fmaxf(a0, a1), b1 = fmaxf(a2, a3);
        float tm = fmaxf(b0, b1);
        unsigned bb = __float_as_uint(tm);
        unsigned bi = (dist[0] == tm) ? (unsigned)tid
                    : (dist[1] == tm) ? (unsigned)(512 + tid)
                    : (dist[2] == tm) ? (unsigned)(1024 + tid)
                    : (dist[3] == tm) ? (unsigned)(1536 + tid)
                    : (dist[4] == tm) ? (unsigned)(2048 + tid)
                    : (dist[5] == tm) ? (unsigned)(2560 + tid)
                    : (dist[6] == tm) ? (unsigned)(3072 + tid)
                    : (unsigned)(3584 + tid);
        unsigned wmax = redux_max_u32(bb);
        unsigned wmin = redux_min_u32((bb == wmax) ? bi : 0xFFFFFFFFu);
        if (lane == 0) red[it & 1][w] = ((unsigned long long)wmax << 32) | (unsigned)(~wmin);
        __syncthreads();
        unsigned long long k = (lane < 16) ? red[it & 1][lane] : 0ull;
        unsigned hi = (unsigned)(k >> 32), lo = (unsigned)k;
        unsigned mhi = redux_max_u32(hi);
        unsigned mlo = redux_max_u32((hi == mhi) ? lo : 0u);
        far = (int)(~mlo);
    }
}

// ---- KNN: exact top-33 via warp-cooperative radix select, drop rank-1 ----
__global__ void __launch_bounds__(256) k_knn(const float* __restrict__ xyz) {
    __shared__ float sx[NN], sy[NN], sz[NN];
    __shared__ int hist[8][256];
    __shared__ int scand[8][33];
    int b = blockIdx.y;
    const float* xb = xyz + (size_t)b*3*NN;
    for (int j = threadIdx.x; j < NN; j += 256) {
        sx[j] = xb[j]; sy[j] = xb[NN+j]; sz[j] = xb[2*NN+j];
    }
    __syncthreads();
    int w = threadIdx.x >> 5, lane = threadIdx.x & 31;
    int q = blockIdx.x*8 + w;
    float qx = d_newxyz[((size_t)b*SS+q)*3+0];
    float qy = d_newxyz[((size_t)b*SS+q)*3+1];
    float qz = d_newxyz[((size_t)b*SS+q)*3+2];
    float sq = __fadd_rn(__fadd_rn(__fmul_rn(qx,qx), __fmul_rn(qy,qy)), __fmul_rn(qz,qz));

    auto ukey = [&](int j) -> unsigned {
        float x = sx[j], y = sy[j], z = sz[j];
        float sn  = __fadd_rn(__fadd_rn(__fmul_rn(x,x), __fmul_rn(y,y)), __fmul_rn(z,z));
        float dot = __fadd_rn(__fadd_rn(__fmul_rn(x,qx), __fmul_rn(y,qy)), __fmul_rn(z,qz));
        float d2  = __fsub_rn(__fadd_rn(sn, sq), __fmul_rn(2.f, dot));
        unsigned bits = __float_as_uint(d2);
        return (bits & 0x80000000u) ? ~bits : (bits | 0x80000000u);
    };

    unsigned prefix = 0;
    int want = 33;
    #pragma unroll
    for (int pass = 3; pass >= 0; pass--) {
        for (int i = lane; i < 256; i += 32) hist[w][i] = 0;
        __syncwarp();
        int shift = pass * 8;
        unsigned pmask = (pass == 3) ? 0u : (0xFFFFFFFFu << (shift + 8));
        for (int s = 0; s < 128; s++) {
            unsigned u = ukey(s*32 + lane);
            if ((u & pmask) == prefix)
                atomicAdd(&hist[w][(u >> shift) & 255], 1);
        }
        __syncwarp();
        int base = lane * 8;
        int cnt8[8]; int csum = 0;
        #pragma unroll
        for (int i = 0; i < 8; i++) { cnt8[i] = hist[w][base+i]; csum += cnt8[i]; }
        int inc = csum;
        #pragma unroll
        for (int o = 1; o < 32; o <<= 1) {
            int v = __shfl_up_sync(0xffffffffu, inc, o);
            if (lane >= o) inc += v;
        }
        int excl = inc - csum;
        unsigned bal = __ballot_sync(0xffffffffu, (excl < want) && (want <= inc));
        int src = __ffs(bal) - 1;
        int wantIn = __shfl_sync(0xffffffffu, want - excl, src);
        int bytev = 0, newwant = 0;
        if (lane == src) {
            int acc = 0; bytev = -1;
            #pragma unroll
            for (int i = 0; i < 8; i++) {
                if (bytev < 0 && acc + cnt8[i] >= wantIn) { bytev = base + i; newwant = wantIn - acc; }
                acc += cnt8[i];
            }
        }
        bytev = __shfl_sync(0xffffffffu, bytev, src);
        newwant = __shfl_sync(0xffffffffu, newwant, src);
        prefix |= ((unsigned)bytev) << shift;
        want = newwant;
        __syncwarp();
    }
    unsigned Tu = prefix;
    int nEq = want;
    int nlt = 0, neq = 0;
    unsigned long long minkey = ~0ull;
    for (int s = 0; s < 128; s++) {
        int j = s*32 + lane;
        unsigned u = ukey(j);
        bool lt = (u < Tu), eq = (u == Tu);
        unsigned bl = __ballot_sync(0xffffffffu, lt);
        unsigned be = __ballot_sync(0xffffffffu, eq);
        unsigned lmask = (1u << lane) - 1u;
        if (lt) {
            int pos = nlt + __popc(bl & lmask);
            scand[w][pos] = j;
            unsigned long long k2 = ((unsigned long long)u << 13) | (unsigned)j;
            if (k2 < minkey) minkey = k2;
        }
        if (eq) {
            int pos = neq + __popc(be & lmask);
            if (pos < nEq) scand[w][(33 - nEq) + pos] = j;
        }
        nlt += __popc(bl);
        neq += __popc(be);
    }
    #pragma unroll
    for (int o = 16; o; o >>= 1) {
        unsigned long long v = __shfl_xor_sync(0xffffffffu, minkey, o);
        if (v < minkey) minkey = v;
    }
    __syncwarp();
    int dropj = (nlt > 0) ? (int)(minkey & 0x1FFFull) : scand[w][33 - nEq];
    int* dst = &d_knn[((size_t)b*SS + q)*KK];
    int v0 = scand[w][lane];
    unsigned hit0 = __ballot_sync(0xffffffffu, v0 == dropj);
    int dropPos = hit0 ? (__ffs(hit0) - 1) : 32;
    if (lane != dropPos) {
        int op = lane - ((lane > dropPos) ? 1 : 0);
        dst[op] = v0;
    }
    if (lane == 0 && dropPos != 32) dst[31] = scand[w][32];
}

// ---- aug features + conv_aug (pre-BN) ----
__global__ void __launch_bounds__(256) k_aug(const float* __restrict__ xyz,
                                             const float* __restrict__ Waug,
                                             const float* __restrict__ baug) {
    __shared__ float sW[320];
    __shared__ float sb[32];
    __shared__ float sx[8][10];
    int tid = threadIdx.x;
    for (int i = tid; i < 320; i += 256) sW[i] = Waug[i];
    if (tid < 32) sb[tid] = baug[tid];
    int kk = tid >> 5, c = tid & 31;
    int p = blockIdx.x*8 + kk;
    int b = p >> 15;
    if (c == 0) {
        int s = (p >> 5) & 1023;
        const float* nx = &d_newxyz[((size_t)b*SS + s)*3];
        float cx = nx[0], cy = nx[1], cz = nx[2];
        int gi = d_knn[p];
        const float* xb = xyz + (size_t)b*3*NN;
        float gx = xb[gi], gy = xb[NN+gi], gz = xb[2*NN+gi];
        float dx = gx-cx, dy = gy-cy, dz = gz-cz;
        float n0 = __fmul_rn(dx,dx), n1 = __fmul_rn(dy,dy), n2 = __fmul_rn(dz,dz);
        float gd = sqrtf(__fadd_rn(__fadd_rn(n0,n1),n2));
        sx[kk][0]=cx; sx[kk][1]=cy; sx[kk][2]=cz;
        sx[kk][3]=gx; sx[kk][4]=gy; sx[kk][5]=gz;
        sx[kk][6]=n0; sx[kk][7]=n1; sx[kk][8]=n2; sx[kk][9]=gd;
    }
    __syncthreads();
    if (c < 7) {
        int src = (c < 6) ? c : 9;
        d_geo[(size_t)p*7 + c] = sx[kk][src];
    }
    float acc = sb[c];
    #pragma unroll
    for (int i = 0; i < 10; i++) acc = fmaf(sx[kk][i], sW[c*10+i], acc);
    d_augy[(size_t)p*32 + c] = acc;
}

// ---- deterministic column stats (small inputs + augy) ----
__global__ void __launch_bounds__(256) k_colstats(const float* __restrict__ Y,
                                                  int M, int C, float* __restrict__ part) {
    int strip = blockIdx.x, nstrip = gridDim.x;
    int rows = M / nstrip;
    int r0 = strip * rows;
    int G = 256 / C;
    int g = threadIdx.x / C, c = threadIdx.x % C;
    float s = 0.f, q = 0.f;
    for (int m = r0 + g; m < r0 + rows; m += G) {
        float v = Y[(size_t)m*C + c];
        s += v; q = fmaf(v, v, q);
    }
    __shared__ float sh[512];
    sh[threadIdx.x] = s; sh[256 + threadIdx.x] = q;
    __syncthreads();
    if (g == 0) {
        for (int gg = 1; gg < G; gg++) { s += sh[gg*C + c]; q += sh[256 + gg*C + c]; }
        part[(size_t)strip*2*C + c]     = s;
        part[(size_t)strip*2*C + C + c] = q;
    }
}

__global__ void k_finalize(const float* __restrict__ part, int nstrip, int M,
                           const float* __restrict__ gamma, const float* __restrict__ beta,
                           float* __restrict__ bnp) {
    int c = threadIdx.x, C = blockDim.x;
    float s = 0.f, q = 0.f;
    for (int j = 0; j < nstrip; j++) {
        s += part[(size_t)j*2*C + c];
        q += part[(size_t)j*2*C + C + c];
    }
    float invM = 1.f / (float)M;
    float mean = s * invM;
    float var = q * invM - mean*mean;
    float scale = gamma[c] * rsqrtf(var + 1e-5f);
    bnp[c] = scale;
    bnp[C + c] = beta[c] - mean*scale;
}

// finalize for GEMM-fused partials — PARALLEL (1024 threads)
__global__ void __launch_bounds__(1024) k_finalize2(const float* __restrict__ part,
                                                    int nby, int gridx, int M, int C,
                                                    const float* __restrict__ gamma,
                                                    const float* __restrict__ beta,
                                                    float* __restrict__ bnp) {
    __shared__ float sh_s[1024], sh_q[1024];
    int tidx = threadIdx.x;
    int G = 1024 / C;
    int g = tidx / C, c = tidx % C;
    int bx = c >> 6, cc = c & 63;
    float s = 0.f, q = 0.f;
    #pragma unroll 4
    for (int by = g; by < nby; by += G) {
        size_t base = ((size_t)(by*gridx + bx))*128;
        s += part[base + cc];
        q += part[base + 64 + cc];
    }
    sh_s[tidx] = s; sh_q[tidx] = q;
    __syncthreads();
    if (g == 0) {
        for (int gg = 1; gg < G; gg++) { s += sh_s[gg*C + c]; q += sh_q[gg*C + c]; }
        float invM = 1.f / (float)M;
        float mean = s * invM;
        float var = q * invM - mean*mean;
        float scale = gamma[c] * rsqrtf(var + 1e-5f);
        bnp[c] = scale;
        bnp[C + c] = beta[c] - mean*scale;
    }
}

// ---- build fx1 ----
__global__ void __launch_bounds__(96) k_fx1() {
    int bs = blockIdx.x, c = threadIdx.x;
    int b = bs >> 10;
    if (c < 64) {
        int gi = d_fpsidx[bs];
        d_fx1[(size_t)bs*96 + c] = d_ptsT[((size_t)b*NN + gi)*64 + c];
    } else {
        int ca = c - 64;
        float sc = d_bnp_aug[ca], sh = d_bnp_aug[32+ca];
        float m = -FLT_MAX;
        for (int k = 0; k < KK; k++) {
            float v = fmaxf(fmaf(d_augy[((size_t)bs*KK + k)*32 + ca], sc, sh), 0.f);
            m = fmaxf(m, v);
        }
        d_fx1[(size_t)bs*96 + c] = m;
    }
}

// ============ pure tf32 tensor GEMM (1 MMA), merged fy path ==========
__device__ __forceinline__ void mma_tf32(float d[4], unsigned a0, unsigned a1,
                                         unsigned a2, unsigned a3,
                                         unsigned b0, unsigned b1) {
    asm volatile(
        "mma.sync.aligned.m16n8k8.row.col.f32.tf32.tf32.f32 "
        "{%0,%1,%2,%3},{%4,%5,%6,%7},{%8,%9},{%0,%1,%2,%3};"
        : "+f"(d[0]), "+f"(d[1]), "+f"(d[2]), "+f"(d[3])
        : "r"(a0), "r"(a1), "r"(a2), "r"(a3), "r"(b0), "r"(b1));
}

__device__ __forceinline__ float tf32_rna(float v) {
    unsigned hb;
    asm("cvt.rna.tf32.f32 %0, %1;" : "=r"(hb) : "f"(v));
    return __uint_as_float(hb);
}

// smem: A buf*2176 + k*136 + r [0,4352); B 4352 + buf*1152 + k*72 + n [4352,6656)
#define TM_SMEM_BYTES (6656*4)

// FYMODE: -1 none; 0 plain Xf; 1 bn+relu(Xf,bnpf). fy blocks: blockIdx.y >= nbyMain.
template<int MODE, int STATS, int FYMODE>
__global__ void __launch_bounds__(256) k_tmma(const float* __restrict__ X,
                                              const float* __restrict__ W,
                                              const float* __restrict__ bias,
                                              float* __restrict__ Y,
                                              int M, int K, int C,
                                              const float* __restrict__ bnp,
                                              float* __restrict__ part,
                                              const float* __restrict__ Xf,
                                              const float* __restrict__ bnpf,
                                              float* __restrict__ Yf,
                                              int nbyMain) {
    extern __shared__ float sm[];
    __shared__ int sGI[128];
    __shared__ float st_s[4][64], st_q[4][64];
    bool isfy = (FYMODE >= 0) && ((int)blockIdx.y >= nbyMain);
    int bm = (isfy ? ((int)blockIdx.y - nbyMain) : (int)blockIdx.y) * 128;
    int bn = blockIdx.x * 64;
    int tid = threadIdx.x;
    if (MODE == 2) {
        if (!isfy && tid < 128) sGI[tid] = d_knn[bm + tid];
        __syncthreads();
    }
    int wid = tid >> 5, lane = tid & 31;
    int wm = wid & 3, wn = wid >> 2;
    int g = lane >> 2, t = lane & 3;

    auto loadA = [&](int r, int k) -> float {
        if (FYMODE >= 0 && isfy) {
            if (k >= K) return 0.f;
            float v = Xf[(size_t)(bm + r)*K + k];
            if (FYMODE == 1) v = fmaxf(fmaf(v, bnpf[k], bnpf[K + k]), 0.f);
            return v;
        }
        if (MODE == 0) {
            return (k < K) ? X[(size_t)(bm + r)*K + k] : 0.f;
        } else if (MODE == 1) {
            if (k >= K) return 0.f;
            float v = X[(size_t)(bm + r)*K + k];
            return fmaxf(fmaf(v, bnp[k], bnp[K + k]), 0.f);
        } else if (MODE == 2) {
            int p = bm + r; int b = p >> 15;
            if (k < 64) return d_ptsT[((size_t)b*NN + sGI[r])*64 + k];
            if (k < 96) {
                int c = k - 64;
                float v = d_augy[(size_t)p*32 + c];
                return fmaxf(fmaf(v, d_bnp_aug[c], d_bnp_aug[32 + c]), 0.f);
            }
            return 0.f;
        } else {
            int p = bm + r;
            if (k < 7) return d_geo[(size_t)p*7 + k];
            if (k < 135) {
                int c = k - 7;
                float v = d_y2[(size_t)p*128 + c];
                float np2 = fmaxf(fmaf(v, bnp[c], bnp[128 + c]), 0.f);
                return np2 - d_cf[(size_t)(p >> 5)*128 + c];
            }
            return 0.f;
        }
    };

    float va[8], vb[4];
    auto prefetch = [&](int k0) {
        #pragma unroll
        for (int u = 0; u < 8; u++) {
            int i = tid + u*256;
            va[u] = loadA(i >> 4, k0 + (i & 15));
        }
        #pragma unroll
        for (int u = 0; u < 4; u++) {
            int i = tid + u*256, kg = k0 + (i & 15);
            vb[u] = (kg < K) ? W[(size_t)(bn + (i >> 4))*K + kg] : 0.f;
        }
    };
    auto store = [&](int buf) {
        #pragma unroll
        for (int u = 0; u < 8; u++) {
            int i = tid + u*256, r = i >> 4, k = i & 15;
            sm[buf*2176 + k*136 + r] = tf32_rna(va[u]);
        }
        #pragma unroll
        for (int u = 0; u < 4; u++) {
            int i = tid + u*256, n = i >> 4, k = i & 15;
            sm[4352 + buf*1152 + k*72 + n] = tf32_rna(vb[u]);
        }
    };

    float d[2][4][4];
    #pragma unroll
    for (int i = 0; i < 2; i++)
        #pragma unroll
        for (int j = 0; j < 4; j++)
            #pragma unroll
            for (int l = 0; l < 4; l++) d[i][j][l] = 0.f;

    int nch = (K + 15) >> 4;
    prefetch(0);
    store(0);
    __syncthreads();

    for (int ch = 0; ch < nch; ch++) {
        int cur = ch & 1;
        if (ch + 1 < nch) prefetch((ch + 1) << 4);
        const float* Ap = &sm[cur*2176];
        const float* Bp = &sm[4352 + cur*1152];
        #pragma unroll
        for (int ks = 0; ks < 16; ks += 8) {
            unsigned ah[2][4], bh[4][2];
            #pragma unroll
            for (int mt = 0; mt < 2; mt++) {
                int r0 = wm*32 + mt*16 + g;
                ah[mt][0] = __float_as_uint(Ap[(ks + t)*136 + r0]);
                ah[mt][1] = __float_as_uint(Ap[(ks + t)*136 + r0 + 8]);
                ah[mt][2] = __float_as_uint(Ap[(ks + t + 4)*136 + r0]);
                ah[mt][3] = __float_as_uint(Ap[(ks + t + 4)*136 + r0 + 8]);
            }
            #pragma unroll
            for (int nt = 0; nt < 4; nt++) {
                int c0 = wn*32 + nt*8 + g;
                bh[nt][0] = __float_as_uint(Bp[(ks + t)*72 + c0]);
                bh[nt][1] = __float_as_uint(Bp[(ks + t + 4)*72 + c0]);
            }
            #pragma unroll
            for (int mt = 0; mt < 2; mt++)
                #pragma unroll
                for (int nt = 0; nt < 4; nt++)
                    mma_tf32(d[mt][nt], ah[mt][0], ah[mt][1], ah[mt][2], ah[mt][3],
                             bh[nt][0], bh[nt][1]);
        }
        if (ch + 1 < nch) {
            store((ch + 1) & 1);
            __syncthreads();
        }
    }

    float* Yp = (FYMODE >= 0 && isfy) ? Yf : Y;
    float csum[4][2], csq[4][2];
    if (STATS) {
        #pragma unroll
        for (int nt = 0; nt < 4; nt++) { csum[nt][0]=csum[nt][1]=csq[nt][0]=csq[nt][1]=0.f; }
    }
    #pragma unroll
    for (int mt = 0; mt < 2; mt++) {
        int r = bm + wm*32 + mt*16 + g;
        #pragma unroll
        for (int nt = 0; nt < 4; nt++) {
            int c0 = bn + wn*32 + nt*8 + 2*t;
            float b0 = bias[c0], b1 = bias[c0 + 1];
            float v0 = d[mt][nt][0] + b0, v1 = d[mt][nt][1] + b1;
            float v2 = d[mt][nt][2] + b0, v3 = d[mt][nt][3] + b1;
            *reinterpret_cast<float2*>(&Yp[(size_t)r*C + c0])       = make_float2(v0, v1);
            *reinterpret_cast<float2*>(&Yp[(size_t)(r + 8)*C + c0]) = make_float2(v2, v3);
            if (STATS) {
                csum[nt][0] += v0 + v2; csum[nt][1] += v1 + v3;
                csq[nt][0]  = fmaf(v0, v0, fmaf(v2, v2, csq[nt][0]));
                csq[nt][1]  = fmaf(v1, v1, fmaf(v3, v3, csq[nt][1]));
            }
        }
    }
    if (STATS) {
        #pragma unroll
        for (int off = 4; off < 32; off <<= 1) {
            #pragma unroll
            for (int nt = 0; nt < 4; nt++) {
                csum[nt][0] += __shfl_xor_sync(0xffffffffu, csum[nt][0], off);
                csum[nt][1] += __shfl_xor_sync(0xffffffffu, csum[nt][1], off);
                csq[nt][0]  += __shfl_xor_sync(0xffffffffu, csq[nt][0], off);
                csq[nt][1]  += __shfl_xor_sync(0xffffffffu, csq[nt][1], off);
            }
        }
        if (lane < 4) {
            #pragma unroll
            for (int nt = 0; nt < 4; nt++) {
                int col = wn*32 + nt*8 + 2*t;
                st_s[wm][col]   = csum[nt][0];
                st_s[wm][col+1] = csum[nt][1];
                st_q[wm][col]   = csq[nt][0];
                st_q[wm][col+1] = csq[nt][1];
            }
        }
        __syncthreads();
        if (!isfy && tid < 128) {
            int col = tid & 63, which = tid >> 6;
            float v = which ? (st_q[0][col] + st_q[1][col] + st_q[2][col] + st_q[3][col])
                            : (st_s[0][col] + st_s[1][col] + st_s[2][col] + st_s[3][col]);
            part[((size_t)(blockIdx.y*gridDim.x + blockIdx.x))*128 + which*64 + col] = v;
        }
    }
}

// ---- centre_feat ----
__global__ void __launch_bounds__(256) k_cf() {
    int i = blockIdx.x*256 + threadIdx.x;
    int c = i & 127;
    d_cf[i] = fmaxf(fmaf(d_fy2[i], d_bnp2f[c], d_bnp2f[128+c]), 0.f);
}

// ---- softmax attention pool + output ----
__global__ void __launch_bounds__(128) k_final(float* __restrict__ out) {
    int bs = blockIdx.x, c = threadIdx.x;
    float s3 = d_bnp3[c], h3 = d_bnp3[128+c];
    float s2 = d_bnp2[c], h2 = d_bnp2[128+c];
    float att[32];
    float m = -FLT_MAX;
    #pragma unroll
    for (int k = 0; k < 32; k++) {
        float w = fmaxf(fmaf(d_y3[((size_t)bs*32 + k)*128 + c], s3, h3), 0.f);
        att[k] = w;
        m = fmaxf(m, w);
    }
    float sum = 0.f;
    #pragma unroll
    for (int k = 0; k < 32; k++) {
        float e = expf(att[k] - m);
        att[k] = e;
        sum += e;
    }
    float pooled = 0.f;
    #pragma unroll
    for (int k = 0; k < 32; k++) {
        float np2 = fmaxf(fmaf(d_y2[((size_t)bs*32 + k)*128 + c], s2, h2), 0.f);
        pooled = fmaf(att[k], np2, pooled);
    }
    float o = d_cf[(size_t)bs*128 + c] + pooled / sum;
    int b = bs >> 10, s = bs & 1023;
    out[24576 + ((size_t)b*128 + c)*1024 + s] = o;
}

extern "C" void kernel_launch(void* const* d_in, const int* in_sizes, int n_in,
                              void* d_out, int out_size) {
    (void)in_sizes; (void)n_in; (void)out_size;
    const float* xyz    = (const float*)d_in[0];
    const float* points = (const float*)d_in[1];
    const float* W_aug  = (const float*)d_in[2];
    const float* b_aug  = (const float*)d_in[3];
    const float* g_aug  = (const float*)d_in[4];
    const float* be_aug = (const float*)d_in[5];
    const float* W1     = (const float*)d_in[6];
    const float* b1     = (const float*)d_in[7];
    const float* g1     = (const float*)d_in[8];
    const float* be1    = (const float*)d_in[9];
    const float* W2     = (const float*)d_in[10];
    const float* b2     = (const float*)d_in[11];
    const float* g2     = (const float*)d_in[12];
    const float* be2    = (const float*)d_in[13];
    const float* W_laa  = (const float*)d_in[14];
    const float* b_laa  = (const float*)d_in[15];
    const float* g_laa  = (const float*)d_in[16];
    const float* be_laa = (const float*)d_in[17];
    float* out = (float*)d_out;

    void *p_augy, *p_fx1, *p_y1, *p_fy1, *p_y2, *p_fy2, *p_y3, *p_part;
    void *p_bna, *p_bn1, *p_bn1f, *p_bn2, *p_bn2f, *p_bn3;
    cudaGetSymbolAddress(&p_augy, d_augy);
    cudaGetSymbolAddress(&p_fx1, d_fx1);
    cudaGetSymbolAddress(&p_y1, d_y1);
    cudaGetSymbolAddress(&p_fy1, d_fy1);
    cudaGetSymbolAddress(&p_y2, d_y2);
    cudaGetSymbolAddress(&p_fy2, d_fy2);
    cudaGetSymbolAddress(&p_y3, d_y3);
    cudaGetSymbolAddress(&p_part, d_part);
    cudaGetSymbolAddress(&p_bna, d_bnp_aug);
    cudaGetSymbolAddress(&p_bn1, d_bnp1);
    cudaGetSymbolAddress(&p_bn1f, d_bnp1f);
    cudaGetSymbolAddress(&p_bn2, d_bnp2);
    cudaGetSymbolAddress(&p_bn2f, d_bnp2f);
    cudaGetSymbolAddress(&p_bn3, d_bnp3);

    cudaFuncSetAttribute((const void*)k_tmma<1,1,1>,  cudaFuncAttributeMaxDynamicSharedMemorySize, TM_SMEM_BYTES);
    cudaFuncSetAttribute((const void*)k_tmma<2,1,0>,  cudaFuncAttributeMaxDynamicSharedMemorySize, TM_SMEM_BYTES);
    cudaFuncSetAttribute((const void*)k_tmma<3,1,-1>, cudaFuncAttributeMaxDynamicSharedMemorySize, TM_SMEM_BYTES);

    k_ptsT<<<dim3(NN/32, 2, BB), dim3(32, 8)>>>(points);
    k_fps<<<BB, 512>>>(xyz, out);
    k_knn<<<dim3(SS/8, BB), 256>>>(xyz);
    k_aug<<<PP/8, 256>>>(xyz, W_aug, b_aug);

    k_colstats<<<1024, 256>>>((const float*)p_augy, PP, 32, (float*)p_part);
    k_finalize<<<1, 32>>>((const float*)p_part, 1024, PP, g_aug, be_aug, (float*)p_bna);

    k_fx1<<<BS, 96>>>();

    // merged: big x1-GEMM (2048 blocks) + fx1 GEMM (64 blocks)
    k_tmma<2,1,0><<<dim3(1, PP/128 + BS/128), 256, TM_SMEM_BYTES>>>(
        nullptr, W1, b1, (float*)p_y1, PP, 96, 64, nullptr, (float*)p_part,
        (const float*)p_fx1, nullptr, (float*)p_fy1, PP/128);
    k_finalize2<<<1, 1024>>>((const float*)p_part, PP/128, 1, PP, 64, g1, be1, (float*)p_bn1);
    k_colstats<<<64, 256>>>((const float*)p_fy1, BS, 64, (float*)p_part);
    k_finalize<<<1, 64>>>((const float*)p_part, 64, BS, g1, be1, (float*)p_bn1f);

    // merged: big y2-GEMM + fy2 GEMM
    k_tmma<1,1,1><<<dim3(2, PP/128 + BS/128), 256, TM_SMEM_BYTES>>>(
        (const float*)p_y1, W2, b2, (float*)p_y2, PP, 64, 128, (const float*)p_bn1, (float*)p_part,
        (const float*)p_fy1, (const float*)p_bn1f, (float*)p_fy2, PP/128);
    k_finalize2<<<1, 1024>>>((const float*)p_part, PP/128, 2, PP, 128, g2, be2, (float*)p_bn2);
    k_colstats<<<64, 256>>>((const float*)p_fy2, BS, 128, (float*)p_part);
    k_finalize<<<1, 128>>>((const float*)p_part, 64, BS, g2, be2, (float*)p_bn2f);

    k_cf<<<BS*128/256, 256>>>();

    k_tmma<3,1,-1><<<dim3(2, PP/128), 256, TM_SMEM_BYTES>>>(
        nullptr, W_laa, b_laa, (float*)p_y3, PP, 135, 128, (const float*)p_bn2, (float*)p_part,
        nullptr, nullptr, nullptr, PP/128);
    k_finalize2<<<1, 1024>>>((const float*)p_part, PP/128, 2, PP, 128, g_laa, be_laa, (float*)p_bn3);

    k_final<<<BS, 128>>>(out);
}

// round 16
// speedup vs baseline: 1.1237x; 1.1237x over previous
#include <cuda_runtime.h>
#include <math.h>
#include <float.h>

#define BB 8
#define NN 4096
#define SS 1024
#define KK 32
#define PP (BB*SS*KK)
#define BS (BB*SS)

__device__ float d_newxyz[BS*3];
__device__ int   d_fpsidx[BS];
__device__ int   d_knn[PP];
__device__ float d_geo[(size_t)PP*7];
__device__ float d_augy[(size_t)PP*32];
__device__ float d_ptsT[(size_t)BB*NN*64];
__device__ float d_fx1[(size_t)BS*96];
__device__ float d_y1[(size_t)PP*64];
__device__ float d_fy1[(size_t)BS*64];
__device__ float d_y2[(size_t)PP*128];
__device__ float d_fy2[(size_t)BS*128];
__device__ float d_cf[(size_t)BS*128];
__device__ float d_y3[(size_t)PP*128];
__device__ float d_part[4096*128];
__device__ float d_bnp_aug[64];
__device__ float d_bnp1[128];
__device__ float d_bnp1f[128];
__device__ float d_bnp2[256];
__device__ float d_bnp2f[256];
__device__ float d_bnp3[256];

// ---- transpose points (B,64,N) -> (B,N,64) ----
__global__ void k_ptsT(const float* __restrict__ pts) {
    __shared__ float t[32][33];
    int b = blockIdx.z, c0 = blockIdx.y*32, n0 = blockIdx.x*32;
    int tx = threadIdx.x, ty = threadIdx.y;
    #pragma unroll
    for (int i = 0; i < 32; i += 8)
        t[ty+i][tx] = pts[(size_t)b*64*NN + (size_t)(c0+ty+i)*NN + n0 + tx];
    __syncthreads();
    #pragma unroll
    for (int i = 0; i < 32; i += 8)
        d_ptsT[((size_t)b*NN + n0+ty+i)*64 + c0+tx] = t[tx][ty+i];
}

__device__ __forceinline__ unsigned redux_max_u32(unsigned v) {
    unsigned r;
    asm volatile("redux.sync.max.u32 %0, %1, 0xffffffff;" : "=r"(r) : "r"(v));
    return r;
}
__device__ __forceinline__ unsigned redux_min_u32(unsigned v) {
    unsigned r;
    asm volatile("redux.sync.min.u32 %0, %1, 0xffffffff;" : "=r"(r) : "r"(v));
    return r;
}

__device__ __forceinline__ unsigned long long pk2(float lo, float hi) {
    unsigned long long r;
    asm("mov.b64 %0, {%1, %2};" : "=l"(r) : "f"(lo), "f"(hi));
    return r;
}
__device__ __forceinline__ void upk2(unsigned long long v, float& lo, float& hi) {
    asm("mov.b64 {%0, %1}, %2;" : "=f"(lo), "=f"(hi) : "l"(v));
}
#define ADD2(o,a,b) asm("add.rn.f32x2 %0, %1, %2;" : "=l"(o) : "l"(a), "l"(b))
#define MUL2(o,a,b) asm("mul.rn.f32x2 %0, %1, %2;" : "=l"(o) : "l"(a), "l"(b))

// ---- FPS: 1024 threads x 4 pts, packed f32x2 distance math (round-14 winner) ----
__global__ void __launch_bounds__(1024) k_fps(const float* __restrict__ xyz,
                                              float* __restrict__ out) {
    int b = blockIdx.x, tid = threadIdx.x;
    int w = tid >> 5, lane = tid & 31;
    const float* xb = xyz + (size_t)b*3*NN;
    unsigned long long pxp[2], pyp[2], pzp[2];
    float dist[4];
    #pragma unroll
    for (int j = 0; j < 2; j++) {
        int n0 = (2*j)*1024 + tid, n1 = (2*j+1)*1024 + tid;
        pxp[j] = pk2(xb[n0],        xb[n1]);
        pyp[j] = pk2(xb[NN+n0],     xb[NN+n1]);
        pzp[j] = pk2(xb[2*NN+n0],   xb[2*NN+n1]);
        dist[2*j] = 1e10f; dist[2*j+1] = 1e10f;
    }
    __shared__ unsigned long long red[2][32];
    int far = 0;
    for (int it = 0; it < SS; it++) {
        float cx = xb[far], cy = xb[NN+far], cz = xb[2*NN+far];
        if (tid == 0) {
            d_fpsidx[b*SS+it] = far;
            d_newxyz[((size_t)b*SS+it)*3+0] = cx;
            d_newxyz[((size_t)b*SS+it)*3+1] = cy;
            d_newxyz[((size_t)b*SS+it)*3+2] = cz;
            out[b*3072 + it]        = cx;
            out[b*3072 + 1024 + it] = cy;
            out[b*3072 + 2048 + it] = cz;
        }
        unsigned long long ncx = pk2(-cx, -cx);
        unsigned long long ncy = pk2(-cy, -cy);
        unsigned long long ncz = pk2(-cz, -cz);
        #pragma unroll
        for (int j = 0; j < 2; j++) {
            unsigned long long dx, dy, dz, mx, my, mz, s;
            ADD2(dx, pxp[j], ncx);
            ADD2(dy, pyp[j], ncy);
            ADD2(dz, pzp[j], ncz);
            MUL2(mx, dx, dx);
            MUL2(my, dy, dy);
            MUL2(mz, dz, dz);
            ADD2(s, mx, my);
            ADD2(s, s, mz);
            float d0, d1; upk2(s, d0, d1);
            dist[2*j]   = fminf(dist[2*j],   d0);
            dist[2*j+1] = fminf(dist[2*j+1], d1);
        }
        float m01 = fmaxf(dist[0], dist[1]);
        float m23 = fmaxf(dist[2], dist[3]);
        float tm  = fmaxf(m01, m23);
        unsigned bb = __float_as_uint(tm);
        unsigned bi = (dist[0] == tm) ? (unsigned)tid
                    : (dist[1] == tm) ? (unsigned)(1024 + tid)
                    : (dist[2] == tm) ? (unsigned)(2048 + tid)
                    : (unsigned)(3072 + tid);
        unsigned wmax = redux_max_u32(bb);
        unsigned wmin = redux_min_u32((bb == wmax) ? bi : 0xFFFFFFFFu);
        if (lane == 0) red[it & 1][w] = ((unsigned long long)wmax << 32) | (unsigned)(~wmin);
        __syncthreads();
        unsigned long long k = red[it & 1][lane];
        unsigned hi = (unsigned)(k >> 32), lo = (unsigned)k;
        unsigned mhi = redux_max_u32(hi);
        unsigned mlo = redux_max_u32((hi == mhi) ? lo : 0u);
        far = (int)(~mlo);
    }
}

// ---- KNN: exact top-33 via warp-cooperative radix select, drop rank-1 ----
__global__ void __launch_bounds__(256) k_knn(const float* __restrict__ xyz) {
    __shared__ float sx[NN], sy[NN], sz[NN];
    __shared__ int hist[8][256];
    __shared__ int scand[8][33];
    int b = blockIdx.y;
    const float* xb = xyz + (size_t)b*3*NN;
    for (int j = threadIdx.x; j < NN; j += 256) {
        sx[j] = xb[j]; sy[j] = xb[NN+j]; sz[j] = xb[2*NN+j];
    }
    __syncthreads();
    int w = threadIdx.x >> 5, lane = threadIdx.x & 31;
    int q = blockIdx.x*8 + w;
    float qx = d_newxyz[((size_t)b*SS+q)*3+0];
    float qy = d_newxyz[((size_t)b*SS+q)*3+1];
    float qz = d_newxyz[((size_t)b*SS+q)*3+2];
    float sq = __fadd_rn(__fadd_rn(__fmul_rn(qx,qx), __fmul_rn(qy,qy)), __fmul_rn(qz,qz));

    auto ukey = [&](int j) -> unsigned {
        float x = sx[j], y = sy[j], z = sz[j];
        float sn  = __fadd_rn(__fadd_rn(__fmul_rn(x,x), __fmul_rn(y,y)), __fmul_rn(z,z));
        float dot = __fadd_rn(__fadd_rn(__fmul_rn(x,qx), __fmul_rn(y,qy)), __fmul_rn(z,qz));
        float d2  = __fsub_rn(__fadd_rn(sn, sq), __fmul_rn(2.f, dot));
        unsigned bits = __float_as_uint(d2);
        return (bits & 0x80000000u) ? ~bits : (bits | 0x80000000u);
    };

    unsigned prefix = 0;
    int want = 33;
    #pragma unroll
    for (int pass = 3; pass >= 0; pass--) {
        for (int i = lane; i < 256; i += 32) hist[w][i] = 0;
        __syncwarp();
        int shift = pass * 8;
        unsigned pmask = (pass == 3) ? 0u : (0xFFFFFFFFu << (shift + 8));
        for (int s = 0; s < 128; s++) {
            unsigned u = ukey(s*32 + lane);
            if ((u & pmask) == prefix)
                atomicAdd(&hist[w][(u >> shift) & 255], 1);
        }
        __syncwarp();
        int base = lane * 8;
        int cnt8[8]; int csum = 0;
        #pragma unroll
        for (int i = 0; i < 8; i++) { cnt8[i] = hist[w][base+i]; csum += cnt8[i]; }
        int inc = csum;
        #pragma unroll
        for (int o = 1; o < 32; o <<= 1) {
            int v = __shfl_up_sync(0xffffffffu, inc, o);
            if (lane >= o) inc += v;
        }
        int excl = inc - csum;
        unsigned bal = __ballot_sync(0xffffffffu, (excl < want) && (want <= inc));
        int src = __ffs(bal) - 1;
        int wantIn = __shfl_sync(0xffffffffu, want - excl, src);
        int bytev = 0, newwant = 0;
        if (lane == src) {
            int acc = 0; bytev = -1;
            #pragma unroll
            for (int i = 0; i < 8; i++) {
                if (bytev < 0 && acc + cnt8[i] >= wantIn) { bytev = base + i; newwant = wantIn - acc; }
                acc += cnt8[i];
            }
        }
        bytev = __shfl_sync(0xffffffffu, bytev, src);
        newwant = __shfl_sync(0xffffffffu, newwant, src);
        prefix |= ((unsigned)bytev) << shift;
        want = newwant;
        __syncwarp();
    }
    unsigned Tu = prefix;
    int nEq = want;
    int nlt = 0, neq = 0;
    unsigned long long minkey = ~0ull;
    for (int s = 0; s < 128; s++) {
        int j = s*32 + lane;
        unsigned u = ukey(j);
        bool lt = (u < Tu), eq = (u == Tu);
        unsigned bl = __ballot_sync(0xffffffffu, lt);
        unsigned be = __ballot_sync(0xffffffffu, eq);
        unsigned lmask = (1u << lane) - 1u;
        if (lt) {
            int pos = nlt + __popc(bl & lmask);
            scand[w][pos] = j;
            unsigned long long k2 = ((unsigned long long)u << 13) | (unsigned)j;
            if (k2 < minkey) minkey = k2;
        }
        if (eq) {
            int pos = neq + __popc(be & lmask);
            if (pos < nEq) scand[w][(33 - nEq) + pos] = j;
        }
        nlt += __popc(bl);
        neq += __popc(be);
    }
    #pragma unroll
    for (int o = 16; o; o >>= 1) {
        unsigned long long v = __shfl_xor_sync(0xffffffffu, minkey, o);
        if (v < minkey) minkey = v;
    }
    __syncwarp();
    int dropj = (nlt > 0) ? (int)(minkey & 0x1FFFull) : scand[w][33 - nEq];
    int* dst = &d_knn[((size_t)b*SS + q)*KK];
    int v0 = scand[w][lane];
    unsigned hit0 = __ballot_sync(0xffffffffu, v0 == dropj);
    int dropPos = hit0 ? (__ffs(hit0) - 1) : 32;
    if (lane != dropPos) {
        int op = lane - ((lane > dropPos) ? 1 : 0);
        dst[op] = v0;
    }
    if (lane == 0 && dropPos != 32) dst[31] = scand[w][32];
}

// ---- aug features + conv_aug (pre-BN) ----
__global__ void __launch_bounds__(256) k_aug(const float* __restrict__ xyz,
                                             const float* __restrict__ Waug,
                                             const float* __restrict__ baug) {
    __shared__ float sW[320];
    __shared__ float sb[32];
    __shared__ float sx[8][10];
    int tid = threadIdx.x;
    for (int i = tid; i < 320; i += 256) sW[i] = Waug[i];
    if (tid < 32) sb[tid] = baug[tid];
    int kk = tid >> 5, c = tid & 31;
    int p = blockIdx.x*8 + kk;
    int b = p >> 15;
    if (c == 0) {
        int s = (p >> 5) & 1023;
        const float* nx = &d_newxyz[((size_t)b*SS + s)*3];
        float cx = nx[0], cy = nx[1], cz = nx[2];
        int gi = d_knn[p];
        const float* xb = xyz + (size_t)b*3*NN;
        float gx = xb[gi], gy = xb[NN+gi], gz = xb[2*NN+gi];
        float dx = gx-cx, dy = gy-cy, dz = gz-cz;
        float n0 = __fmul_rn(dx,dx), n1 = __fmul_rn(dy,dy), n2 = __fmul_rn(dz,dz);
        float gd = sqrtf(__fadd_rn(__fadd_rn(n0,n1),n2));
        sx[kk][0]=cx; sx[kk][1]=cy; sx[kk][2]=cz;
        sx[kk][3]=gx; sx[kk][4]=gy; sx[kk][5]=gz;
        sx[kk][6]=n0; sx[kk][7]=n1; sx[kk][8]=n2; sx[kk][9]=gd;
    }
    __syncthreads();
    if (c < 7) {
        int src = (c < 6) ? c : 9;
        d_geo[(size_t)p*7 + c] = sx[kk][src];
    }
    float acc = sb[c];
    #pragma unroll
    for (int i = 0; i < 10; i++) acc = fmaf(sx[kk][i], sW[c*10+i], acc);
    d_augy[(size_t)p*32 + c] = acc;
}

// ---- deterministic column stats (small inputs + augy) ----
__global__ void __launch_bounds__(256) k_colstats(const float* __restrict__ Y,
                                                  int M, int C, float* __restrict__ part) {
    int strip = blockIdx.x, nstrip = gridDim.x;
    int rows = M / nstrip;
    int r0 = strip * rows;
    int G = 256 / C;
    int g = threadIdx.x / C, c = threadIdx.x % C;
    float s = 0.f, q = 0.f;
    for (int m = r0 + g; m < r0 + rows; m += G) {
        float v = Y[(size_t)m*C + c];
        s += v; q = fmaf(v, v, q);
    }
    __shared__ float sh[512];
    sh[threadIdx.x] = s; sh[256 + threadIdx.x] = q;
    __syncthreads();
    if (g == 0) {
        for (int gg = 1; gg < G; gg++) { s += sh[gg*C + c]; q += sh[256 + gg*C + c]; }
        part[(size_t)strip*2*C + c]     = s;
        part[(size_t)strip*2*C + C + c] = q;
    }
}

__global__ void k_finalize(const float* __restrict__ part, int nstrip, int M,
                           const float* __restrict__ gamma, const float* __restrict__ beta,
                           float* __restrict__ bnp) {
    int c = threadIdx.x, C = blockDim.x;
    float s = 0.f, q = 0.f;
    for (int j = 0; j < nstrip; j++) {
        s += part[(size_t)j*2*C + c];
        q += part[(size_t)j*2*C + C + c];
    }
    float invM = 1.f / (float)M;
    float mean = s * invM;
    float var = q * invM - mean*mean;
    float scale = gamma[c] * rsqrtf(var + 1e-5f);
    bnp[c] = scale;
    bnp[C + c] = beta[c] - mean*scale;
}

// finalize for GEMM-fused partials — PARALLEL (1024 threads)
__global__ void __launch_bounds__(1024) k_finalize2(const float* __restrict__ part,
                                                    int nby, int gridx, int M, int C,
                                                    const float* __restrict__ gamma,
                                                    const float* __restrict__ beta,
                                                    float* __restrict__ bnp) {
    __shared__ float sh_s[1024], sh_q[1024];
    int tidx = threadIdx.x;
    int G = 1024 / C;
    int g = tidx / C, c = tidx % C;
    int bx = c >> 6, cc = c & 63;
    float s = 0.f, q = 0.f;
    #pragma unroll 4
    for (int by = g; by < nby; by += G) {
        size_t base = ((size_t)(by*gridx + bx))*128;
        s += part[base + cc];
        q += part[base + 64 + cc];
    }
    sh_s[tidx] = s; sh_q[tidx] = q;
    __syncthreads();
    if (g == 0) {
        for (int gg = 1; gg < G; gg++) { s += sh_s[gg*C + c]; q += sh_q[gg*C + c]; }
        float invM = 1.f / (float)M;
        float mean = s * invM;
        float var = q * invM - mean*mean;
        float scale = gamma[c] * rsqrtf(var + 1e-5f);
        bnp[c] = scale;
        bnp[C + c] = beta[c] - mean*scale;
    }
}

// ---- build fx1 ----
__global__ void __launch_bounds__(96) k_fx1() {
    int bs = blockIdx.x, c = threadIdx.x;
    int b = bs >> 10;
    if (c < 64) {
        int gi = d_fpsidx[bs];
        d_fx1[(size_t)bs*96 + c] = d_ptsT[((size_t)b*NN + gi)*64 + c];
    } else {
        int ca = c - 64;
        float sc = d_bnp_aug[ca], sh = d_bnp_aug[32+ca];
        float m = -FLT_MAX;
        for (int k = 0; k < KK; k++) {
            float v = fmaxf(fmaf(d_augy[((size_t)bs*KK + k)*32 + ca], sc, sh), 0.f);
            m = fmaxf(m, v);
        }
        d_fx1[(size_t)bs*96 + c] = m;
    }
}

// ============ pure tf32 tensor GEMM (1 MMA per tile pair) ==========
__device__ __forceinline__ void mma_tf32(float d[4], unsigned a0, unsigned a1,
                                         unsigned a2, unsigned a3,
                                         unsigned b0, unsigned b1) {
    asm volatile(
        "mma.sync.aligned.m16n8k8.row.col.f32.tf32.tf32.f32 "
        "{%0,%1,%2,%3},{%4,%5,%6,%7},{%8,%9},{%0,%1,%2,%3};"
        : "+f"(d[0]), "+f"(d[1]), "+f"(d[2]), "+f"(d[3])
        : "r"(a0), "r"(a1), "r"(a2), "r"(a3), "r"(b0), "r"(b1));
}

__device__ __forceinline__ float tf32_rna(float v) {
    unsigned hb;
    asm("cvt.rna.tf32.f32 %0, %1;" : "=r"(hb) : "f"(v));
    return __uint_as_float(hb);
}

// smem: A buf*2176 + k*136 + r [0,4352); B 4352 + buf*1152 + k*72 + n
#define TM_SMEM_BYTES (6656*4)

template<int MODE, int STATS>
__global__ void __launch_bounds__(256) k_tmma(const float* __restrict__ X,
                                              const float* __restrict__ W,
                                              const float* __restrict__ bias,
                                              float* __restrict__ Y,
                                              int M, int K, int C,
                                              const float* __restrict__ bnp,
                                              float* __restrict__ part) {
    extern __shared__ float sm[];
    __shared__ int sGI[128];
    __shared__ float st_s[4][64], st_q[4][64];
    int bm = blockIdx.y * 128;
    int bn = blockIdx.x * 64;
    int tid = threadIdx.x;
    if (MODE == 2) {
        if (tid < 128) sGI[tid] = d_knn[bm + tid];
        __syncthreads();
    }
    int wid = tid >> 5, lane = tid & 31;
    int wm = wid & 3, wn = wid >> 2;
    int g = lane >> 2, t = lane & 3;

    auto loadA = [&](int r, int k) -> float {
        if (MODE == 0) {
            return (k < K) ? X[(size_t)(bm + r)*K + k] : 0.f;
        } else if (MODE == 1) {
            if (k >= K) return 0.f;
            float v = X[(size_t)(bm + r)*K + k];
            return fmaxf(fmaf(v, bnp[k], bnp[K + k]), 0.f);
        } else if (MODE == 2) {
            int p = bm + r; int b = p >> 15;
            if (k < 64) return d_ptsT[((size_t)b*NN + sGI[r])*64 + k];
            if (k < 96) {
                int c = k - 64;
                float v = d_augy[(size_t)p*32 + c];
                return fmaxf(fmaf(v, d_bnp_aug[c], d_bnp_aug[32 + c]), 0.f);
            }
            return 0.f;
        } else {
            int p = bm + r;
            if (k < 7) return d_geo[(size_t)p*7 + k];
            if (k < 135) {
                int c = k - 7;
                float v = d_y2[(size_t)p*128 + c];
                float np2 = fmaxf(fmaf(v, bnp[c], bnp[128 + c]), 0.f);
                return np2 - d_cf[(size_t)(p >> 5)*128 + c];
            }
            return 0.f;
        }
    };

    float va[8], vb[4];
    auto prefetch = [&](int k0) {
        #pragma unroll
        for (int u = 0; u < 8; u++) {
            int i = tid + u*256;
            va[u] = loadA(i >> 4, k0 + (i & 15));
        }
        #pragma unroll
        for (int u = 0; u < 4; u++) {
            int i = tid + u*256, kg = k0 + (i & 15);
            vb[u] = (kg < K) ? W[(size_t)(bn + (i >> 4))*K + kg] : 0.f;
        }
    };
    auto store = [&](int buf) {
        #pragma unroll
        for (int u = 0; u < 8; u++) {
            int i = tid + u*256, r = i >> 4, k = i & 15;
            sm[buf*2176 + k*136 + r] = tf32_rna(va[u]);
        }
        #pragma unroll
        for (int u = 0; u < 4; u++) {
            int i = tid + u*256, n = i >> 4, k = i & 15;
            sm[4352 + buf*1152 + k*72 + n] = tf32_rna(vb[u]);
        }
    };

    float d[2][4][4];
    #pragma unroll
    for (int i = 0; i < 2; i++)
        #pragma unroll
        for (int j = 0; j < 4; j++)
            #pragma unroll
            for (int l = 0; l < 4; l++) d[i][j][l] = 0.f;

    int nch = (K + 15) >> 4;
    prefetch(0);
    store(0);
    __syncthreads();

    for (int ch = 0; ch < nch; ch++) {
        int cur = ch & 1;
        if (ch + 1 < nch) prefetch((ch + 1) << 4);
        const float* Ap = &sm[cur*2176];
        const float* Bp = &sm[4352 + cur*1152];
        #pragma unroll
        for (int ks = 0; ks < 16; ks += 8) {
            unsigned ah[2][4], bh[4][2];
            #pragma unroll
            for (int mt = 0; mt < 2; mt++) {
                int r0 = wm*32 + mt*16 + g;
                ah[mt][0] = __float_as_uint(Ap[(ks + t)*136 + r0]);
                ah[mt][1] = __float_as_uint(Ap[(ks + t)*136 + r0 + 8]);
                ah[mt][2] = __float_as_uint(Ap[(ks + t + 4)*136 + r0]);
                ah[mt][3] = __float_as_uint(Ap[(ks + t + 4)*136 + r0 + 8]);
            }
            #pragma unroll
            for (int nt = 0; nt < 4; nt++) {
                int c0 = wn*32 + nt*8 + g;
                bh[nt][0] = __float_as_uint(Bp[(ks + t)*72 + c0]);
                bh[nt][1] = __float_as_uint(Bp[(ks + t + 4)*72 + c0]);
            }
            #pragma unroll
            for (int mt = 0; mt < 2; mt++)
                #pragma unroll
                for (int nt = 0; nt < 4; nt++)
                    mma_tf32(d[mt][nt], ah[mt][0], ah[mt][1], ah[mt][2], ah[mt][3],
                             bh[nt][0], bh[nt][1]);
        }
        if (ch + 1 < nch) {
            store((ch + 1) & 1);
            __syncthreads();
        }
    }

    float csum[4][2], csq[4][2];
    if (STATS) {
        #pragma unroll
        for (int nt = 0; nt < 4; nt++) { csum[nt][0]=csum[nt][1]=csq[nt][0]=csq[nt][1]=0.f; }
    }
    #pragma unroll
    for (int mt = 0; mt < 2; mt++) {
        int r = bm + wm*32 + mt*16 + g;
        #pragma unroll
        for (int nt = 0; nt < 4; nt++) {
            int c0 = bn + wn*32 + nt*8 + 2*t;
            float b0 = bias[c0], b1 = bias[c0 + 1];
            float v0 = d[mt][nt][0] + b0, v1 = d[mt][nt][1] + b1;
            float v2 = d[mt][nt][2] + b0, v3 = d[mt][nt][3] + b1;
            *reinterpret_cast<float2*>(&Y[(size_t)r*C + c0])       = make_float2(v0, v1);
            *reinterpret_cast<float2*>(&Y[(size_t)(r + 8)*C + c0]) = make_float2(v2, v3);
            if (STATS) {
                csum[nt][0] += v0 + v2; csum[nt][1] += v1 + v3;
                csq[nt][0]  = fmaf(v0, v0, fmaf(v2, v2, csq[nt][0]));
                csq[nt][1]  = fmaf(v1, v1, fmaf(v3, v3, csq[nt][1]));
            }
        }
    }
    if (STATS) {
        #pragma unroll
        for (int off = 4; off < 32; off <<= 1) {
            #pragma unroll
            for (int nt = 0; nt < 4; nt++) {
                csum[nt][0] += __shfl_xor_sync(0xffffffffu, csum[nt][0], off);
                csum[nt][1] += __shfl_xor_sync(0xffffffffu, csum[nt][1], off);
                csq[nt][0]  += __shfl_xor_sync(0xffffffffu, csq[nt][0], off);
                csq[nt][1]  += __shfl_xor_sync(0xffffffffu, csq[nt][1], off);
            }
        }
        if (lane < 4) {
            #pragma unroll
            for (int nt = 0; nt < 4; nt++) {
                int col = wn*32 + nt*8 + 2*t;
                st_s[wm][col]   = csum[nt][0];
                st_s[wm][col+1] = csum[nt][1];
                st_q[wm][col]   = csq[nt][0];
                st_q[wm][col+1] = csq[nt][1];
            }
        }
        __syncthreads();
        if (tid < 128) {
            int col = tid & 63, which = tid >> 6;
            float v = which ? (st_q[0][col] + st_q[1][col] + st_q[2][col] + st_q[3][col])
                            : (st_s[0][col] + st_s[1][col] + st_s[2][col] + st_s[3][col]);
            part[((size_t)(blockIdx.y*gridDim.x + blockIdx.x))*128 + which*64 + col] = v;
        }
    }
}

// ---- fp32 SGEMM kept for the small (BS-row) GEMMs ----
template<int BN, int TN, int MODE>
__global__ void __launch_bounds__(256) k_gemm2(const float* __restrict__ X,
                                               const float* __restrict__ W,
                                               const float* __restrict__ bias,
                                               float* __restrict__ Y,
                                               int M, int K, int C,
                                               const float* __restrict__ bnp) {
    constexpr int LB = (BN*16)/256;
    __shared__ __align__(16) float As[2][16][132];
    __shared__ __align__(16) float Bs[2][16][BN+4];
    int bm = blockIdx.y * 128;
    int bn = blockIdx.x * BN;
    int tid = threadIdx.x;
    int tx = tid & 15, ty = tid >> 4;

    auto loadA = [&](int r, int k) -> float {
        if (MODE == 0) {
            return (k < K) ? X[(size_t)(bm + r)*K + k] : 0.f;
        } else {
            if (k >= K) return 0.f;
            float v = X[(size_t)(bm + r)*K + k];
            return fmaxf(fmaf(v, bnp[k], bnp[K + k]), 0.f);
        }
    };

    float acc[8][TN];
    #pragma unroll
    for (int i = 0; i < 8; i++)
        #pragma unroll
        for (int j = 0; j < TN; j++) acc[i][j] = 0.f;

    int nch = (K + 15) >> 4;
    #pragma unroll
    for (int u = 0; u < 8; u++) {
        int i = tid + u*256, r = i >> 4, k = i & 15;
        As[0][k][r] = loadA(r, k);
    }
    #pragma unroll
    for (int u = 0; u < LB; u++) {
        int i = tid + u*256, n = i >> 4, k = i & 15;
        Bs[0][k][n] = (k < K) ? W[(size_t)(bn + n)*K + k] : 0.f;
    }
    __syncthreads();

    float ra[8], rb[LB];
    for (int c = 0; c < nch; c++) {
        int cur = c & 1;
        if (c + 1 < nch) {
            int k0 = (c + 1) << 4;
            #pragma unroll
            for (int u = 0; u < 8; u++) {
                int i = tid + u*256, r = i >> 4, kg = k0 + (i & 15);
                ra[u] = loadA(r, kg);
            }
            #pragma unroll
            for (int u = 0; u < LB; u++) {
                int i = tid + u*256, n = i >> 4, kg = k0 + (i & 15);
                rb[u] = (kg < K) ? W[(size_t)(bn + n)*K + kg] : 0.f;
            }
        }
        #pragma unroll
        for (int kk = 0; kk < 16; kk++) {
            float4 a0 = *reinterpret_cast<const float4*>(&As[cur][kk][ty*8]);
            float4 a1 = *reinterpret_cast<const float4*>(&As[cur][kk][ty*8 + 4]);
            float av[8] = {a0.x, a0.y, a0.z, a0.w, a1.x, a1.y, a1.z, a1.w};
            float bv[TN];
            float4 b0 = *reinterpret_cast<const float4*>(&Bs[cur][kk][tx*TN]);
            bv[0] = b0.x; bv[1] = b0.y; bv[2] = b0.z; bv[3] = b0.w;
            if (TN == 8) {
                float4 b1 = *reinterpret_cast<const float4*>(&Bs[cur][kk][tx*TN + 4]);
                bv[4] = b1.x; bv[5] = b1.y; bv[6] = b1.z; bv[7] = b1.w;
            }
            #pragma unroll
            for (int i = 0; i < 8; i++)
                #pragma unroll
                for (int j = 0; j < TN; j++)
                    acc[i][j] = fmaf(av[i], bv[j], acc[i][j]);
        }
        if (c + 1 < nch) {
            int nb = (c + 1) & 1;
            #pragma unroll
            for (int u = 0; u < 8; u++) {
                int i = tid + u*256;
                As[nb][i & 15][i >> 4] = ra[u];
            }
            #pragma unroll
            for (int u = 0; u < LB; u++) {
                int i = tid + u*256;
                Bs[nb][i & 15][i >> 4] = rb[u];
            }
            __syncthreads();
        }
    }
    #pragma unroll
    for (int i = 0; i < 8; i++) {
        int row = bm + ty*8 + i;
        #pragma unroll
        for (int j = 0; j < TN; j++) {
            int col = bn + tx*TN + j;
            Y[(size_t)row*C + col] = acc[i][j] + bias[col];
        }
    }
}

// ---- centre_feat ----
__global__ void __launch_bounds__(256) k_cf() {
    int i = blockIdx.x*256 + threadIdx.x;
    int c = i & 127;
    d_cf[i] = fmaxf(fmaf(d_fy2[i], d_bnp2f[c], d_bnp2f[128+c]), 0.f);
}

// ---- softmax attention pool + output (fast exp) ----
__global__ void __launch_bounds__(128) k_final(float* __restrict__ out) {
    int bs = blockIdx.x, c = threadIdx.x;
    float s3 = d_bnp3[c], h3 = d_bnp3[128+c];
    float s2 = d_bnp2[c], h2 = d_bnp2[128+c];
    float att[32];
    float m = -FLT_MAX;
    #pragma unroll
    for (int k = 0; k < 32; k++) {
        float w = fmaxf(fmaf(d_y3[((size_t)bs*32 + k)*128 + c], s3, h3), 0.f);
        att[k] = w;
        m = fmaxf(m, w);
    }
    float sum = 0.f;
    #pragma unroll
    for (int k = 0; k < 32; k++) {
        float e = __expf(att[k] - m);
        att[k] = e;
        sum += e;
    }
    float pooled = 0.f;
    #pragma unroll
    for (int k = 0; k < 32; k++) {
        float np2 = fmaxf(fmaf(d_y2[((size_t)bs*32 + k)*128 + c], s2, h2), 0.f);
        pooled = fmaf(att[k], np2, pooled);
    }
    float o = d_cf[(size_t)bs*128 + c] + pooled / sum;
    int b = bs >> 10, s = bs & 1023;
    out[24576 + ((size_t)b*128 + c)*1024 + s] = o;
}

extern "C" void kernel_launch(void* const* d_in, const int* in_sizes, int n_in,
                              void* d_out, int out_size) {
    (void)in_sizes; (void)n_in; (void)out_size;
    const float* xyz    = (const float*)d_in[0];
    const float* points = (const float*)d_in[1];
    const float* W_aug  = (const float*)d_in[2];
    const float* b_aug  = (const float*)d_in[3];
    const float* g_aug  = (const float*)d_in[4];
    const float* be_aug = (const float*)d_in[5];
    const float* W1     = (const float*)d_in[6];
    const float* b1     = (const float*)d_in[7];
    const float* g1     = (const float*)d_in[8];
    const float* be1    = (const float*)d_in[9];
    const float* W2     = (const float*)d_in[10];
    const float* b2     = (const float*)d_in[11];
    const float* g2     = (const float*)d_in[12];
    const float* be2    = (const float*)d_in[13];
    const float* W_laa  = (const float*)d_in[14];
    const float* b_laa  = (const float*)d_in[15];
    const float* g_laa  = (const float*)d_in[16];
    const float* be_laa = (const float*)d_in[17];
    float* out = (float*)d_out;

    void *p_augy, *p_fx1, *p_y1, *p_fy1, *p_y2, *p_fy2, *p_y3, *p_part;
    void *p_bna, *p_bn1, *p_bn1f, *p_bn2, *p_bn2f, *p_bn3;
    cudaGetSymbolAddress(&p_augy, d_augy);
    cudaGetSymbolAddress(&p_fx1, d_fx1);
    cudaGetSymbolAddress(&p_y1, d_y1);
    cudaGetSymbolAddress(&p_fy1, d_fy1);
    cudaGetSymbolAddress(&p_y2, d_y2);
    cudaGetSymbolAddress(&p_fy2, d_fy2);
    cudaGetSymbolAddress(&p_y3, d_y3);
    cudaGetSymbolAddress(&p_part, d_part);
    cudaGetSymbolAddress(&p_bna, d_bnp_aug);
    cudaGetSymbolAddress(&p_bn1, d_bnp1);
    cudaGetSymbolAddress(&p_bn1f, d_bnp1f);
    cudaGetSymbolAddress(&p_bn2, d_bnp2);
    cudaGetSymbolAddress(&p_bn2f, d_bnp2f);
    cudaGetSymbolAddress(&p_bn3, d_bnp3);

    cudaFuncSetAttribute((const void*)k_tmma<1,1>, cudaFuncAttributeMaxDynamicSharedMemorySize, TM_SMEM_BYTES);
    cudaFuncSetAttribute((const void*)k_tmma<2,1>, cudaFuncAttributeMaxDynamicSharedMemorySize, TM_SMEM_BYTES);
    cudaFuncSetAttribute((const void*)k_tmma<3,1>, cudaFuncAttributeMaxDynamicSharedMemorySize, TM_SMEM_BYTES);

    k_ptsT<<<dim3(NN/32, 2, BB), dim3(32, 8)>>>(points);
    k_fps<<<BB, 1024>>>(xyz, out);
    k_knn<<<dim3(SS/8, BB), 256>>>(xyz);
    k_aug<<<PP/8, 256>>>(xyz, W_aug, b_aug);

    k_colstats<<<1024, 256>>>((const float*)p_augy, PP, 32, (float*)p_part);
    k_finalize<<<1, 32>>>((const float*)p_part, 1024, PP, g_aug, be_aug, (float*)p_bna);

    k_fx1<<<BS, 96>>>();

    k_tmma<2,1><<<dim3(1, PP/128), 256, TM_SMEM_BYTES>>>(nullptr, W1, b1, (float*)p_y1, PP, 96, 64, nullptr, (float*)p_part);
    k_finalize2<<<1, 1024>>>((const float*)p_part, PP/128, 1, PP, 64, g1, be1, (float*)p_bn1);

    k_gemm2<64,4,0><<<dim3(1, BS/128), 256>>>((const float*)p_fx1, W1, b1, (float*)p_fy1, BS, 96, 64, nullptr);
    k_colstats<<<64, 256>>>((const float*)p_fy1, BS, 64, (float*)p_part);
    k_finalize<<<1, 64>>>((const float*)p_part, 64, BS, g1, be1, (float*)p_bn1f);

    k_tmma<1,1><<<dim3(2, PP/128), 256, TM_SMEM_BYTES>>>((const float*)p_y1, W2, b2, (float*)p_y2, PP, 64, 128, (const float*)p_bn1, (float*)p_part);
    k_finalize2<<<1, 1024>>>((const float*)p_part, PP/128, 2, PP, 128, g2, be2, (float*)p_bn2);

    k_gemm2<128,8,1><<<dim3(1, BS/128), 256>>>((const float*)p_fy1, W2, b2, (float*)p_fy2, BS, 64, 128, (const float*)p_bn1f);
    k_colstats<<<64, 256>>>((const float*)p_fy2, BS, 128, (float*)p_part);
    k_finalize<<<1, 128>>>((const float*)p_part, 64, BS, g2, be2, (float*)p_bn2f);

    k_cf<<<BS*128/256, 256>>>();

    k_tmma<3,1><<<dim3(2, PP/128), 256, TM_SMEM_BYTES>>>(nullptr, W_laa, b_laa, (float*)p_y3, PP, 135, 128, (const float*)p_bn2, (float*)p_part);
    k_finalize2<<<1, 1024>>>((const float*)p_part, PP/128, 2, PP, 128, g_laa, be_laa, (float*)p_bn3);

    k_final<<<BS, 128>>>(out);
}